// round 15
// baseline (speedup 1.0000x reference)
#include <cuda_runtime.h>
#include <cuda_bf16.h>
#include <cstdint>

// Problem constants (fixed by the reference)
#define B_SEG   16
#define D_F     128            // fine feature dim  (32 float4)
#define D_C     256            // coarse feature dim (64 float4)
#define D_OUT   (D_C + D_F)    // 384

// One full wave on 148 SMs at occupancy 2 with 1024-thread CTAs: 296 CTAs.
// (Same 64 warps/SM as before, but 2 completion units per SM instead of 8
// -> collapses the cross-CTA L1tex-queue completion-spread term.)
#define NTHREADS 1024
#define NT_C    33             // coarse tiles  (byte share ~11.1%)
#define NT_F    263            // fine tiles
#define NBLK    (NT_C + NT_F)  // 296

// Self-restoring device state (zero at module load; each segment's last
// contributor finalizes that segment and resets its state, so every graph
// replay sees zeros again).
__device__ float        g_scratch[B_SEG * D_OUT];
__device__ unsigned int g_segcnt[B_SEG];

// Tile index containing global row r for a tiling of n rows into NT tiles
// with boundaries floor(t*n/NT).
__device__ __forceinline__ int tile_of(int r, int NT, long long n) {
    return (int)(((long long)(r + 1) * NT - 1) / n);
}

// ---------------------------------------------------------------------------
// Specialized work loop: FCOLS float4 per row, LANES row lanes, OBASE output
// column offset. All addressing/strides are compile-time constants.
// ---------------------------------------------------------------------------
template<int FCOLS, int LANES, int OBASE>
__device__ __forceinline__
void run_path(const float4* __restrict__ feats,
              float* __restrict__ out,
              const int* scumC, const int* scumF,
              float4* shred, bool* sfin,
              int r0, int r1, int n_c, int n_f) {
    const int tid = threadIdx.x;
    const int c   = tid % FCOLS;
    const int rr  = tid / FCOLS;
    const int* scum = (OBASE == 0) ? scumC : scumF;
    const float4* base = feats + c;

    int s = 0;
    while (scum[s + 1] <= r0) ++s;

    while (r0 < r1) {
        int e = scum[s + 1]; if (e > r1) e = r1;

        float4 acc = make_float4(0.f, 0.f, 0.f, 0.f);
#pragma unroll 4
        for (int r = r0 + rr; r < e; r += LANES) {
            float4 v = __ldcs(base + (size_t)r * FCOLS);
            acc.x += v.x; acc.y += v.y; acc.z += v.z; acc.w += v.w;
        }

        // ---- block flush of this segment run ----
        shred[tid] = acc;
        __syncthreads();
        if (rr == 0) {
            float4 t = shred[c];
#pragma unroll
            for (int k = 1; k < LANES; ++k) {
                float4 w = shred[k * FCOLS + c];
                t.x += w.x; t.y += w.y; t.z += w.z; t.w += w.w;
            }
            float* o = g_scratch + s * D_OUT + OBASE + c * 4;
            atomicAdd(o + 0, t.x);
            atomicAdd(o + 1, t.y);
            atomicAdd(o + 2, t.z);
            atomicAdd(o + 3, t.w);
        }
        __threadfence();   // release our sums before the counter bump
        __syncthreads();

        // ---- per-segment completion counter; last contributor finalizes ----
        if (tid == 0) {
            int cA = tile_of(scumC[s + 1] - 1, NT_C, n_c)
                   - tile_of(scumC[s],         NT_C, n_c) + 1;
            int cB = tile_of(scumF[s + 1] - 1, NT_F, n_f)
                   - tile_of(scumF[s],         NT_F, n_f) + 1;
            unsigned int expected = (unsigned int)(cA + cB);
            unsigned int old = atomicAdd(&g_segcnt[s], 1u);
            *sfin = (old == expected - 1u);
        }
        __syncthreads();

        if (*sfin) {
            __threadfence();   // acquire: all contributors' atomics visible
            for (int i = tid; i < D_OUT; i += NTHREADS) {
                int len = (i < D_C) ? (scumC[s + 1] - scumC[s])
                                    : (scumF[s + 1] - scumF[s]);
                float v = __ldcg(&g_scratch[s * D_OUT + i]);
                out[s * D_OUT + i] = v / (float)len;
                g_scratch[s * D_OUT + i] = 0.0f;
            }
            if (tid == 0) g_segcnt[s] = 0u;
        }
        __syncthreads();

        r0 = e; ++s;
    }
}

__global__ __launch_bounds__(NTHREADS, 2)
void pare_fused_kernel(const float4* __restrict__ feats_c,
                       const float4* __restrict__ feats_f,
                       const int* __restrict__ lengths_c,
                       const int* __restrict__ lengths_f,
                       float* __restrict__ out,
                       int n_c, int n_f) {
    __shared__ float4 shred[NTHREADS];
    __shared__ int    scumC[B_SEG + 1];
    __shared__ int    scumF[B_SEG + 1];
    __shared__ bool   sfin;
    const int tid  = threadIdx.x;
    const int lane = tid & 31;

    // ---- parallel prologue: both cumsums via warp shfl scans ----
    {
        int vc = (lane < B_SEG) ? __ldg(lengths_c + lane) : 0;
        int vf = (lane < B_SEG) ? __ldg(lengths_f + lane) : 0;
#pragma unroll
        for (int o = 1; o < B_SEG; o <<= 1) {
            int nc2 = __shfl_up_sync(0xFFFFFFFFu, vc, o);
            int nf2 = __shfl_up_sync(0xFFFFFFFFu, vf, o);
            if (lane >= o) { vc += nc2; vf += nf2; }
        }
        if (lane < B_SEG) { scumC[lane + 1] = vc; scumF[lane + 1] = vf; }
        if (lane == 0)    { scumC[0] = 0;        scumF[0] = 0; }
        __syncwarp();
    }

    if (blockIdx.x < NT_C) {
        const int t = blockIdx.x;
        int r0 = (int)(((long long)t)       * n_c / NT_C);
        int r1 = (int)(((long long)(t + 1)) * n_c / NT_C);
        run_path<64, 16, 0>(feats_c, out, scumC, scumF, shred, &sfin,
                            r0, r1, n_c, n_f);
    } else {
        const int t = blockIdx.x - NT_C;
        int r0 = (int)(((long long)t)       * n_f / NT_F);
        int r1 = (int)(((long long)(t + 1)) * n_f / NT_F);
        run_path<32, 32, D_C>(feats_f, out, scumC, scumF, shred, &sfin,
                              r0, r1, n_c, n_f);
    }
}

// ---------------------------------------------------------------------------
extern "C" void kernel_launch(void* const* d_in, const int* in_sizes, int n_in,
                              void* d_out, int out_size) {
    const float* feats_f   = (const float*)d_in[0];   // [524288, 128]
    const float* feats_c   = (const float*)d_in[1];   // [32768, 256]
    const int*   lengths_f = (const int*)d_in[2];     // [16]
    const int*   lengths_c = (const int*)d_in[3];     // [16]
    float* out = (float*)d_out;                       // [16, 384]

    const int n_f = in_sizes[0] / D_F;   // total fine rows
    const int n_c = in_sizes[1] / D_C;   // total coarse rows

    pare_fused_kernel<<<NBLK, NTHREADS>>>((const float4*)feats_c,
                                          (const float4*)feats_f,
                                          lengths_c, lengths_f, out, n_c, n_f);
}